// round 14
// baseline (speedup 1.0000x reference)
#include <cuda_runtime.h>
#include <cuda_bf16.h>

typedef unsigned long long u64;

#define SEQ    1024
#define BATCH  512
#define NT     64
#define CH     8
#define NCHUNK (SEQ / CH)   /* 128 */
#define WPB    4            /* warps per block */
#define BPW    2            /* batches per warp (dual chain) */
#define BPB    (WPB * BPW)  /* 8 batches per block */
#define NBLK   (BATCH / BPB)  /* 64 blocks */

__device__ float    g_num[BATCH];
__device__ float    g_den[BATCH];
__device__ unsigned g_cnt;   /* zero-initialized; self-resets each launch */

__device__ __forceinline__ __nv_bfloat162 u2b(unsigned u) {
    union { unsigned u; __nv_bfloat162 b; } c; c.u = u; return c.b;
}

// ---------------------------------------------------------------------------
// Dual-chain fused kernel: one WARP advances TWO batches (shared E regs).
// Lane j owns columns j and j+32 of each batch. Alpha as bf16x2 in smem
// (slot i = rows (i, i+32)). The two chains' STS->LDS->HFMA2 streams
// interleave inside the warp, hiding each other's latency (the kernel is
// latency-bound at 1 warp/SMSP). Renorm every 8 steps by alpha slot 0.
// Fused gold-path numerators + last-block final reduction.
// ---------------------------------------------------------------------------
__global__ __launch_bounds__(128, 1) void fused_kernel(
    const float* __restrict__ em,
    const void* __restrict__ tags_raw,
    const int* __restrict__ mask,
    const float* __restrict__ startT,
    const float* __restrict__ endT,
    const float* __restrict__ trans,
    float* __restrict__ out)
{
    const int w  = threadIdx.x >> 5;   // warp in block: 0..3
    const int j  = threadIdx.x & 31;   // lane
    const int gw = blockIdx.x * WPB + w;
    const int b0 = 2 * gw;
    const int b1 = 2 * gw + 1;

    // ---- tags dtype detect (jax x64 -> int64, default -> int32) ----
    const int*       tags32 = (const int*)tags_raw;
    const long long* tags64 = (const long long*)tags_raw;
    unsigned nz = __ballot_sync(0xffffffffu, tags32[2 * j + 1] != 0);
    const int is64 = (nz == 0);

    // ---- E pairs bf16x2 (shared by both chains): 64 regs total ----
    __nv_bfloat162 EPa[32], EPb[32];
    #pragma unroll
    for (int i = 0; i < 32; i++) {
        EPa[i] = __floats2bfloat162_rn(__expf(trans[i * NT + j]),
                                       __expf(trans[(i + 32) * NT + j]));
        EPb[i] = __floats2bfloat162_rn(__expf(trans[i * NT + j + 32]),
                                       __expf(trans[(i + 32) * NT + j + 32]));
    }

    __shared__ __align__(16) __nv_bfloat162 a_s[WPB][BPW][2][32];
    __shared__ short stags[BPB][SEQ];
    __shared__ __align__(8) char smask[BPB][SEQ];

    const int s0 = w * BPW;      // smem batch slots
    const int s1 = w * BPW + 1;

    // ---- preload tags + mask for both batches ----
    int mcnt0 = 0, mcnt1 = 0;
    #pragma unroll
    for (int t0 = 0; t0 < SEQ; t0 += 32) {
        int t = t0 + j;
        int mv0 = mask[t * BATCH + b0];
        int mv1 = mask[t * BATCH + b1];
        smask[s0][t] = (char)mv0;  mcnt0 += mv0;
        smask[s1][t] = (char)mv1;  mcnt1 += mv1;
        size_t i0 = (size_t)t * BATCH + b0;
        size_t i1 = (size_t)t * BATCH + b1;
        stags[s0][t] = (short)(is64 ? (int)tags64[i0] : tags32[i0]);
        stags[s1][t] = (short)(is64 ? (int)tags64[i1] : tags32[i1]);
    }

    // ---- stage chunk 0 raw emissions (both batches) ----
    float e0a[CH], e0b[CH], e1a[CH], e1b[CH];
    #pragma unroll
    for (int c = 0; c < CH; c++) {
        size_t base0 = ((size_t)c * BATCH + b0) * NT;
        size_t base1 = ((size_t)c * BATCH + b1) * NT;
        e0a[c] = em[base0 + j];
        e0b[c] = em[base0 + j + 32];
        e1a[c] = em[base1 + j];
        e1b[c] = em[base1 + j + 32];
    }

    // alpha0 for both chains
    float p0a = __expf(startT[j] + e0a[0]);
    float p0b = __expf(startT[j + 32] + e0b[0]);
    float p1a = __expf(startT[j] + e1a[0]);
    float p1b = __expf(startT[j + 32] + e1b[0]);
    a_s[w][0][0][j] = __floats2bfloat162_rn(p0a, p0b);
    a_s[w][1][0][j] = __floats2bfloat162_rn(p1a, p1b);
    __syncwarp();

    float logacc0 = 0.f, logacc1 = 0.f;
    float rs0 = 1.0f, rs1 = 1.0f;
    int   p   = 0;

    // numerator pipeline state, both batches (slice t = k*32 + j, k < 32)
    float score0 = 0.f, score1 = 0.f;
    float tv0 = 0.f, ev0 = 0.f, tv1 = 0.f, ev1 = 0.f;
    int   pm0 = 0, pm1 = 0;

    for (int k = 0; k < NCHUNK; k++) {
        // issue raw emission loads for chunk k+1 (both batches)
        float l0a[CH], l0b[CH], l1a[CH], l1b[CH];
        if (k + 1 < NCHUNK) {
            const size_t base = (size_t)(k + 1) * CH;
            #pragma unroll
            for (int c = 0; c < CH; c++) {
                size_t o0 = ((base + c) * BATCH + b0) * NT;
                size_t o1 = ((base + c) * BATCH + b1) * NT;
                l0a[c] = em[o0 + j];
                l0b[c] = em[o0 + j + 32];
                l1a[c] = em[o1 + j];
                l1b[c] = em[o1 + j + 32];
            }
        }

        // mask bytes for this chunk (one LDS.64 per batch)
        const u64 mw0 = *(const u64*)&smask[s0][k * CH];
        const u64 mw1 = *(const u64*)&smask[s1][k * CH];

        // numerators: consume last chunk's gathers, issue this chunk's
        if (k >= 1 && k <= 32) {
            score0 += pm0 ? (tv0 + ev0) : 0.f;
            score1 += pm1 ? (tv1 + ev1) : 0.f;
        }
        if (k < 32) {
            int t    = k * 32 + j;
            int cur0 = stags[s0][t];
            int cur1 = stags[s1][t];
            if (t == 0) {
                tv0 = startT[cur0];  ev0 = em[(size_t)b0 * NT + cur0];  pm0 = 1;
                tv1 = startT[cur1];  ev1 = em[(size_t)b1 * NT + cur1];  pm1 = 1;
            } else {
                pm0 = smask[s0][t];
                tv0 = trans[stags[s0][t - 1] * NT + cur0];
                ev0 = em[((size_t)t * BATCH + b0) * NT + cur0];
                pm1 = smask[s1][t];
                tv1 = trans[stags[s1][t - 1] * NT + cur1];
                ev1 = em[((size_t)t * BATCH + b1) * NT + cur1];
            }
        }

        const int c0i = (k == 0) ? 1 : 0;
        #pragma unroll
        for (int c = 0; c < CH; c++) {
            if (c < c0i) continue;

            const int m0 = (int)((mw0 >> (8 * c)) & 0xff);
            const int m1 = (int)((mw1 >> (8 * c)) & 0xff);

            float ea0 = __expf(e0a[c]);
            float eb0 = __expf(e0b[c]);
            float ea1 = __expf(e1a[c]);
            float eb1 = __expf(e1b[c]);

            const uint4* ap0 = (const uint4*)&a_s[w][0][p][0];
            const uint4* ap1 = (const uint4*)&a_s[w][1][p][0];
            __nv_bfloat162 z = __floats2bfloat162_rn(0.f, 0.f);
            __nv_bfloat162 A0[4] = {z, z, z, z}, B0[4] = {z, z, z, z};
            __nv_bfloat162 A1[4] = {z, z, z, z}, B1[4] = {z, z, z, z};
            #pragma unroll
            for (int q = 0; q < 8; q++) {      // 8 x LDS.128 per chain
                uint4 v0 = ap0[q];
                uint4 v1 = ap1[q];
                __nv_bfloat162 c00 = u2b(v0.x), c01 = u2b(v0.y),
                               c02 = u2b(v0.z), c03 = u2b(v0.w);
                __nv_bfloat162 c10 = u2b(v1.x), c11 = u2b(v1.y),
                               c12 = u2b(v1.z), c13 = u2b(v1.w);
                const int s = 4 * q;
                A0[0] = __hfma2(c00, EPa[s + 0], A0[0]);
                A0[1] = __hfma2(c01, EPa[s + 1], A0[1]);
                A0[2] = __hfma2(c02, EPa[s + 2], A0[2]);
                A0[3] = __hfma2(c03, EPa[s + 3], A0[3]);
                B0[0] = __hfma2(c00, EPb[s + 0], B0[0]);
                B0[1] = __hfma2(c01, EPb[s + 1], B0[1]);
                B0[2] = __hfma2(c02, EPb[s + 2], B0[2]);
                B0[3] = __hfma2(c03, EPb[s + 3], B0[3]);
                A1[0] = __hfma2(c10, EPa[s + 0], A1[0]);
                A1[1] = __hfma2(c11, EPa[s + 1], A1[1]);
                A1[2] = __hfma2(c12, EPa[s + 2], A1[2]);
                A1[3] = __hfma2(c13, EPa[s + 3], A1[3]);
                B1[0] = __hfma2(c10, EPb[s + 0], B1[0]);
                B1[1] = __hfma2(c11, EPb[s + 1], B1[1]);
                B1[2] = __hfma2(c12, EPb[s + 2], B1[2]);
                B1[3] = __hfma2(c13, EPb[s + 3], B1[3]);
            }
            __nv_bfloat162 sA0 = __hadd2(__hadd2(A0[0], A0[1]), __hadd2(A0[2], A0[3]));
            __nv_bfloat162 sB0 = __hadd2(__hadd2(B0[0], B0[1]), __hadd2(B0[2], B0[3]));
            __nv_bfloat162 sA1 = __hadd2(__hadd2(A1[0], A1[1]), __hadd2(A1[2], A1[3]));
            __nv_bfloat162 sB1 = __hadd2(__hadd2(B1[0], B1[1]), __hadd2(B1[2], B1[3]));
            float d0A = __low2float(sA0) + __high2float(sA0);
            float d0B = __low2float(sB0) + __high2float(sB0);
            float d1A = __low2float(sA1) + __high2float(sA1);
            float d1B = __low2float(sB1) + __high2float(sB1);

            float v0a = m0 ? d0A * (ea0 * rs0) : p0a * rs0;
            float v0b = m0 ? d0B * (eb0 * rs0) : p0b * rs0;
            float v1a = m1 ? d1A * (ea1 * rs1) : p1a * rs1;
            float v1b = m1 ? d1B * (eb1 * rs1) : p1b * rs1;

            a_s[w][0][p ^ 1][j] = __floats2bfloat162_rn(v0a, v0b);
            a_s[w][1][p ^ 1][j] = __floats2bfloat162_rn(v1a, v1b);
            p0a = v0a;  p0b = v0b;
            p1a = v1a;  p1b = v1b;
            __syncwarp();
            p ^= 1;

            if (c == 0) {   // t % 8 == 0: renorm each chain by its alpha[0]
                float az0 = __low2float(a_s[w][0][p][0]);
                float az1 = __low2float(a_s[w][1][p][0]);
                rs0 = __fdividef(1.0f, az0);
                rs1 = __fdividef(1.0f, az1);
                logacc0 += __logf(az0);
                logacc1 += __logf(az1);
            } else {
                rs0 = 1.0f;
                rs1 = 1.0f;
            }
        }

        // roll staged emissions
        if (k + 1 < NCHUNK) {
            #pragma unroll
            for (int c = 0; c < CH; c++) {
                e0a[c] = l0a[c];  e0b[c] = l0b[c];
                e1a[c] = l1a[c];  e1b[c] = l1b[c];
            }
        }
    }

    // ---- denominator epilogues ----
    float ef_a = __expf(endT[j]);
    float ef_b = __expf(endT[j + 32]);
    float sd0 = p0a * ef_a + p0b * ef_b;
    float sd1 = p1a * ef_a + p1b * ef_b;
    #pragma unroll
    for (int o = 16; o; o >>= 1) {
        sd0 += __shfl_xor_sync(0xffffffffu, sd0, o);
        sd1 += __shfl_xor_sync(0xffffffffu, sd1, o);
    }
    if (j == 0) {
        g_den[b0] = logacc0 + __logf(sd0);
        g_den[b1] = logacc1 + __logf(sd1);
    }

    // ---- numerator epilogues ----
    #pragma unroll
    for (int o = 16; o; o >>= 1) {
        score0 += __shfl_down_sync(0xffffffffu, score0, o);
        score1 += __shfl_down_sync(0xffffffffu, score1, o);
        mcnt0  += __shfl_down_sync(0xffffffffu, mcnt0, o);
        mcnt1  += __shfl_down_sync(0xffffffffu, mcnt1, o);
    }
    if (j == 0) {
        g_num[b0] = score0 + endT[stags[s0][mcnt0 - 1]];
        g_num[b1] = score1 + endT[stags[s1][mcnt1 - 1]];
    }

    // ---- last-block final reduction (deterministic: fixed sum order) ----
    __threadfence();
    __syncthreads();
    __shared__ int is_last;
    if (threadIdx.x == 0) {
        unsigned prev = atomicAdd(&g_cnt, 1u);
        is_last = (prev == NBLK - 1);
    }
    __syncthreads();
    if (is_last) {
        __threadfence();
        int tid = threadIdx.x;  // 0..127
        float v = 0.f;
        #pragma unroll
        for (int r = 0; r < BATCH / 128; r++) {
            int i = tid + r * 128;
            v += g_num[i] - g_den[i];
        }
        #pragma unroll
        for (int o = 16; o; o >>= 1)
            v += __shfl_down_sync(0xffffffffu, v, o);
        __shared__ float ws[4];
        if ((tid & 31) == 0) ws[tid >> 5] = v;
        __syncthreads();
        if (tid == 0) {
            out[0] = (ws[0] + ws[1]) + (ws[2] + ws[3]);
            g_cnt = 0;   // reset for next graph replay
        }
    }
}

// ---------------------------------------------------------------------------
// inputs (metadata order): emissions f32, tags i64-or-i32, mask i32,
//                          start_transitions f32, end_transitions f32,
//                          transitions f32.  output: f32 scalar.
// ---------------------------------------------------------------------------
extern "C" void kernel_launch(void* const* d_in, const int* in_sizes, int n_in,
                              void* d_out, int out_size)
{
    const float* em     = (const float*)d_in[0];
    const void*  tags   = d_in[1];
    const int*   mask   = (const int*)d_in[2];
    const float* startT = (const float*)d_in[3];
    const float* endT   = (const float*)d_in[4];
    const float* trans  = (const float*)d_in[5];
    float*       out    = (float*)d_out;

    fused_kernel<<<NBLK, 32 * WPB>>>(em, tags, mask, startT, endT, trans, out);
}